// round 14
// baseline (speedup 1.0000x reference)
#include <cuda_runtime.h>

// Voronoi nearest-site via fine-grid candidate LUT, ALL tables in shared
// memory at FULL occupancy: 512-thread CTAs, 4 CTAs/SM (2048 thr/SM), smem
// 41KB/CTA (164KB/SM of 227KB). Random 4B gathers hit the smem crossbar
// (~4 conflict phases/warp) instead of L1TEX (~32 wavefronts/warp) -- the
// dominant cost term of the L1-resident champion.
// Reference-exact fp32 compare:
//   a  = rn(rn(x0^2) + rn(x1^2))
//   e  = fmaf(x1, sy, rn(x0*sx))
//   d2 = rn(rn(a - 2*e) + cs),  cs = rn(rn(sx^2) + rn(sy^2))
//   argmin: ascending candidate order, strict <  (lowest-index tie-break)

#define GR 96
#define NS 100
#define NCELL (GR * GR)

__device__ unsigned int g_grid[NCELL];
__device__ float4 g_cand[NS];   // sx, sy, cs, 0
__device__ float4 g_rgb[NS];    // r, g, b, 0

__global__ void build_lut(const float* __restrict__ p) {
    __shared__ float sp[2 * NS];
    for (int i = threadIdx.x; i < 2 * NS; i += blockDim.x) {
        int s = i >> 1;
        sp[i] = p[1 + 5 * s + (i & 1)];
    }
    __syncthreads();

    int cell = blockIdx.x * blockDim.x + threadIdx.x;
    if (cell < NCELL) {
        if (cell < NS) {
            float sx = sp[2 * cell], sy = sp[2 * cell + 1];
            float cs = __fadd_rn(__fmul_rn(sx, sx), __fmul_rn(sy, sy));
            g_cand[cell] = make_float4(sx, sy, cs, 0.0f);
            g_rgb[cell]  = make_float4(p[3 + 5 * cell], p[4 + 5 * cell], p[5 + 5 * cell], 0.0f);
        }

        int gy = cell / GR;
        int gx = cell - gy * GR;
        float cx = (gx + 0.5f) * (1.0f / GR);
        float cy = (gy + 0.5f) * (1.0f / GR);

        // 5x5 coarse window: contains the nearest site (d <= 0.1415) and the
        // whole candidate band (reach < 0.2).
        int ci = (int)(cx * 10.0f), cj = (int)(cy * 10.0f);
        int i0 = max(0, ci - 2), i1 = min(9, ci + 2);
        int j0 = max(0, cj - 2), j1 = min(9, cj + 2);

        float best = 3.4e38f;
        for (int ii = i0; ii <= i1; ii++)
            for (int jj = j0; jj <= j1; jj++) {
                int s = ii * 10 + jj;
                float dx = cx - sp[2 * s];
                float dy = cy - sp[2 * s + 1];
                best = fminf(best, fmaf(dx, dx, dy * dy));
            }

        // Band: d(c,s) < d(c,s*) + 2r + slack. 2r = sqrt(2)/96 = 0.0147314;
        // slack 1e-4 covers the reference formula's ~4e-7 d2 noise.
        float thr = sqrtf(best) + 0.0147314f + 1e-4f;
        float thr2 = thr * thr;

        unsigned int entry = 0;
        int cnt = 0;
        for (int ii = i0; ii <= i1; ii++)
            for (int jj = j0; jj <= j1; jj++) {   // ascending site ids
                int s = ii * 10 + jj;
                float dx = cx - sp[2 * s];
                float dy = cy - sp[2 * s + 1];
                float d2 = fmaf(dx, dx, dy * dy);
                if (d2 <= thr2) {
                    if (cnt < 4) entry |= ((unsigned int)s) << (8 * cnt);
                    cnt++;
                }
            }
        if (cnt > 4) {
            entry = (entry & 0xFFu) | 0x0000FE00u | 0x00FF0000u | 0xFF000000u; // 5x5 fallback
        } else {
            for (int k = cnt; k < 4; k++) entry |= 0xFFu << (8 * k);
        }
        g_grid[cell] = entry;
    }

#if __CUDA_ARCH__ >= 900
    cudaTriggerProgrammaticLaunchCompletion();
#endif
}

__device__ __forceinline__ void eval_cand(
    unsigned int c, float px, float py, float a,
    const float4* __restrict__ scand, float& bd, int& bi)
{
    float4 s = scand[c];
    float ee = __fmaf_rn(py, s.y, __fmul_rn(px, s.x));
    float d2 = __fadd_rn(__fsub_rn(a, __fmul_rn(2.0f, ee)), s.z);
    if (d2 < bd) { bd = d2; bi = (int)c; }
}

__device__ __forceinline__ float4 lookup_one(
    float px, float py,
    const unsigned int* __restrict__ sgrid,
    const float4* __restrict__ scand,
    const float4* __restrict__ srgb)
{
    int cx = (int)(px * (float)GR);   // px in [0,1) -> 0..GR-1
    int cy = (int)(py * (float)GR);
    unsigned int e = sgrid[cy * GR + cx];

    int idx = (int)(e & 0xFFu);
    if ((e >> 8) != 0x00FFFFFFu) {
        float a = __fadd_rn(__fmul_rn(px, px), __fmul_rn(py, py));
        float bd = 3.4e38f;
        int bi = 0;
        if (((e >> 8) & 0xFFu) == 0xFEu) {
            // Rare: 5x5 coarse-neighborhood scan (ascending ids).
            int ci = (int)(px * 10.0f);
            int cj = (int)(py * 10.0f);
            int i1 = min(9, ci + 2), j0 = max(0, cj - 2), j1 = min(9, cj + 2);
            for (int ii = max(0, ci - 2); ii <= i1; ii++)
                for (int jj = j0; jj <= j1; jj++)
                    eval_cand((unsigned int)(ii * 10 + jj), px, py, a, scand, bd, bi);
        } else {
            #pragma unroll
            for (int k = 0; k < 4; k++) {
                unsigned int c = (e >> (8 * k)) & 0xFFu;
                if (c == 0xFFu) break;
                eval_cand(c, px, py, a, scand, bd, bi);
            }
        }
        idx = bi;
    }
    return srgb[idx];
}

__global__ void __launch_bounds__(512, 4) voronoi_main(
    const float2* __restrict__ x, float* __restrict__ out, int n)
{
    __shared__ unsigned int sgrid[NCELL];   // 36864 B
    __shared__ float4 scand[NS];            //  1600 B
    __shared__ float4 srgb[NS];             //  1600 B

#if __CUDA_ARCH__ >= 900
    cudaGridDependencySynchronize();   // PDL: wait for build_lut results
#endif
    {
        const uint4* gg = (const uint4*)g_grid;
        uint4* sg = (uint4*)sgrid;
        for (int i = threadIdx.x; i < NCELL / 4; i += 512) sg[i] = gg[i];
        if (threadIdx.x < NS) {
            scand[threadIdx.x] = g_cand[threadIdx.x];
            srgb[threadIdx.x]  = g_rgb[threadIdx.x];
        }
    }
    __syncthreads();

    int tid = blockIdx.x * blockDim.x + threadIdx.x;
    int stride = gridDim.x * blockDim.x;

    for (int i = tid; i < n; i += stride) {
        float2 pt = __ldcs(&x[i]);             // streaming: don't pollute L1
        float4 c = lookup_one(pt.x, pt.y, sgrid, scand, srgb);
        __stcs(&out[3 * i + 0], c.x);          // streaming stores
        __stcs(&out[3 * i + 1], c.y);
        __stcs(&out[3 * i + 2], c.z);
    }
}

extern "C" void kernel_launch(void* const* d_in, const int* in_sizes, int n_in,
                              void* d_out, int out_size) {
    const float2* x = (const float2*)d_in[0];
    const float*  p = (const float*)d_in[1];
    float* out = (float*)d_out;
    int n = in_sizes[0] / 2;

    build_lut<<<(NCELL + 127) / 128, 128>>>(p);

    // PDL launch: voronoi_main's launch/staging overlaps build_lut.
    cudaLaunchConfig_t cfg = {};
    cfg.gridDim  = dim3(592, 1, 1);    // 4 CTAs/SM x 148 SMs = one full wave
    cfg.blockDim = dim3(512, 1, 1);
    cudaLaunchAttribute attrs[1];
    attrs[0].id = cudaLaunchAttributeProgrammaticStreamSerialization;
    attrs[0].val.programmaticStreamSerializationAllowed = 1;
    cfg.attrs = attrs;
    cfg.numAttrs = 1;
    cudaLaunchKernelEx(&cfg, voronoi_main, x, out, n);
}